// round 10
// baseline (speedup 1.0000x reference)
#include <cuda_runtime.h>
#include <cstdint>

// out[o,m,n] = sum_{kh,j} w0[o,kh,j] * S[m, n+kh, j]       (n >= 1)
// out[o,m,0] = sum_{kh,j} w0[o,kh,j] * S0[m, kh, j]
// Scratch: Sg[((m*14 + j)*80) + r], r in [0,63] = S rows, [64,72] = S0 rows.

__device__ __align__(16) float Sg[56 * 14 * 80];

__device__ __forceinline__ uint64_t pack2(float s) {
    uint64_t r;
    unsigned u = __float_as_uint(s);
    asm("mov.b64 %0, {%1, %1};" : "=l"(r) : "r"(u));
    return r;
}
__device__ __forceinline__ void ffma2(uint64_t& d, uint64_t a, uint64_t b) {
    asm("fma.rn.f32x2 %0, %1, %2, %0;" : "+l"(d) : "l"(a), "l"(b));
}
__device__ __forceinline__ void addf2(uint64_t& d, uint64_t a) {
    asm("add.rn.f32x2 %0, %0, %1;" : "+l"(d) : "l"(a));
}
__device__ __forceinline__ float2 unpack2(uint64_t v) {
    unsigned lo, hi;
    asm("mov.b64 {%0, %1}, %2;" : "=r"(lo), "=r"(hi) : "l"(v));
    return make_float2(__uint_as_float(lo), __uint_as_float(hi));
}

// ───────────── Kernel 1: build S ─────────────
#define XP 68
__global__ __launch_bounds__(160)
void build_S_kernel(const float* __restrict__ x, const float* __restrict__ w1)
{
    __shared__ float xp[24 * XP];   // xp[i][h+5] = x[i,m,h], pads zero
    __shared__ float w1s[24 * 28];
    const int m = blockIdx.x, jg = blockIdx.y, tid = threadIdx.x;

    for (int t = tid; t < 24 * XP; t += 160) xp[t] = 0.0f;
    for (int t = tid; t < 24 * 28; t += 160) w1s[t] = w1[t];
    __syncthreads();
    for (int t = tid; t < 24 * 56; t += 160) {
        const int i = t / 56, h = t % 56;
        xp[i * XP + 5 + h] = x[i * 3136 + m * 56 + h];
    }
    __syncthreads();

    if (tid < 146) {
        const int j = jg * 2 + tid / 73;
        const int r = tid % 73;
        float a0 = 0.f, a1 = 0.f, a2 = 0.f, a3 = 0.f;
        if (r < 64) {
            #pragma unroll
            for (int i = 0; i < 24; i += 2) {
                a0 = fmaf(xp[i * XP + r + 1],     w1s[i * 28 + j],          a0);
                a1 = fmaf(xp[i * XP + r],         w1s[i * 28 + 14 + j],     a1);
                a2 = fmaf(xp[(i+1) * XP + r + 1], w1s[(i+1) * 28 + j],      a2);
                a3 = fmaf(xp[(i+1) * XP + r],     w1s[(i+1) * 28 + 14 + j], a3);
            }
        } else {
            const int kh = r - 64;
            if (kh >= 4) {
                #pragma unroll
                for (int i = 0; i < 24; i += 2) {
                    a0 = fmaf(xp[i * XP + kh + 1],     w1s[i * 28 + j],     a0);
                    a2 = fmaf(xp[(i+1) * XP + kh + 1], w1s[(i+1) * 28 + j], a2);
                }
            }
            if (kh <= 4) {
                #pragma unroll
                for (int i = 0; i < 24; i += 2) {
                    a1 = fmaf(xp[i * XP + kh + 56],     w1s[i * 28 + 14 + j],     a1);
                    a3 = fmaf(xp[(i+1) * XP + kh + 56], w1s[(i+1) * 28 + 14 + j], a3);
                }
            }
        }
        Sg[(m * 14 + j) * 80 + r] = (a0 + a2) + (a1 + a3);
    }
}

// ───────────── Kernel 2: stencil register-blocked contraction ─────────────
// grid (56 m, 3 og of 32 o), block 224 = ow(8, fast) × np(14) × jh(2).
// Thread: 4 o × 4 n, jh half of j (7). Per (j,kh): 1 LDS.128 + 8 FFMA2 (w reused 4n).
__global__ __launch_bounds__(224)
void contract_kernel(const float* __restrict__ w0, float* __restrict__ out)
{
    __shared__ __align__(16) uint64_t Sd[14 * 80];    // dup-pair S: 8.96 KB
    __shared__ __align__(16) float w0s[126 * 32];     // [k][32 o]: 16.1 KB
    __shared__ __align__(16) uint64_t red[112 * 8];   // jh partials: 7 KB

    const int m   = blockIdx.x;
    const int og  = blockIdx.y;          // 0..2
    const int tid = threadIdx.x;

    // stage S (coalesced f32 reads -> dup-pair u64)
    for (int t = tid; t < 1120; t += 224)
        Sd[t] = pack2(Sg[m * 1120 + t]);
    // stage w0: ol-fast -> conflict-free STS (LDG uncoalesced but MLP-deep)
    for (int t = tid; t < 126 * 32; t += 224) {
        const int ol = t & 31, k = t >> 5;
        w0s[k * 32 + ol] = w0[(og * 32 + ol) * 126 + k];
    }
    __syncthreads();

    const int ow = tid & 7;              // 0..7 -> o quad
    const int np = (tid >> 3) % 14;      // 0..13 -> n quad (n = 4np..4np+3)
    const int jh = tid / 112;            // 0..1 -> j half
    const int rb  = 4 * np;
    const int rb0 = (np == 0) ? 64 : rb; // n==0 window -> S0 rows

    uint64_t acc[4][2] = {{0,0},{0,0},{0,0},{0,0}};

    #pragma unroll
    for (int j = 0; j < 7; j++) {
        const int jj = jh * 7 + j;
        const uint64_t* __restrict__ sb  = Sd + jj * 80 + rb;
        const uint64_t* __restrict__ s0b = Sd + jj * 80 + rb0;

        uint64_t sw[12];
        #pragma unroll
        for (int d = 0; d < 12; d++) sw[d] = sb[d];
        uint64_t s0w[9];
        #pragma unroll
        for (int d = 0; d < 9; d++) s0w[d] = s0b[d];

        #pragma unroll
        for (int kh = 0; kh < 9; kh++) {
            const ulonglong2 wv = *reinterpret_cast<const ulonglong2*>(
                w0s + (kh * 14 + jj) * 32 + ow * 4);
            ffma2(acc[0][0], wv.x, s0w[kh]);
            ffma2(acc[0][1], wv.y, s0w[kh]);
            ffma2(acc[1][0], wv.x, sw[1 + kh]);
            ffma2(acc[1][1], wv.y, sw[1 + kh]);
            ffma2(acc[2][0], wv.x, sw[2 + kh]);
            ffma2(acc[2][1], wv.y, sw[2 + kh]);
            ffma2(acc[3][0], wv.x, sw[3 + kh]);
            ffma2(acc[3][1], wv.y, sw[3 + kh]);
        }
    }

    const int rr = tid % 112;
    if (jh == 1) {
        ulonglong2* dst = reinterpret_cast<ulonglong2*>(&red[rr * 8]);
        dst[0] = make_ulonglong2(acc[0][0], acc[0][1]);
        dst[1] = make_ulonglong2(acc[1][0], acc[1][1]);
        dst[2] = make_ulonglong2(acc[2][0], acc[2][1]);
        dst[3] = make_ulonglong2(acc[3][0], acc[3][1]);
    }
    __syncthreads();

    if (jh == 0) {
        const ulonglong2* src = reinterpret_cast<const ulonglong2*>(&red[rr * 8]);
        #pragma unroll
        for (int nn = 0; nn < 4; nn++) {
            const ulonglong2 p = src[nn];
            addf2(acc[nn][0], p.x);
            addf2(acc[nn][1], p.y);
        }
        // stores: per o, float4 over the 4 consecutive n (16B-aligned: n0 % 4 == 0)
        const int ob = og * 32 + ow * 4;
        const int n0 = 4 * np;
        float* op = out + m * 56 + n0;
        #pragma unroll
        for (int opair = 0; opair < 2; opair++) {
            const float2 u0 = unpack2(acc[0][opair]);
            const float2 u1 = unpack2(acc[1][opair]);
            const float2 u2 = unpack2(acc[2][opair]);
            const float2 u3 = unpack2(acc[3][opair]);
            *reinterpret_cast<float4*>(op + (ob + 2 * opair)     * 3136) =
                make_float4(u0.x, u1.x, u2.x, u3.x);
            *reinterpret_cast<float4*>(op + (ob + 2 * opair + 1) * 3136) =
                make_float4(u0.y, u1.y, u2.y, u3.y);
        }
    }
}

extern "C" void kernel_launch(void* const* d_in, const int* in_sizes, int n_in,
                              void* d_out, int out_size)
{
    const float* x = (const float*)d_in[0];
    const float* w0;
    const float* w1;
    if (in_sizes[1] == 12096) { w0 = (const float*)d_in[1]; w1 = (const float*)d_in[2]; }
    else                      { w0 = (const float*)d_in[2]; w1 = (const float*)d_in[1]; }
    float* out = (float*)d_out;

    build_S_kernel<<<dim3(56, 7), 160>>>(x, w1);
    contract_kernel<<<dim3(56, 3), 224>>>(w0, out);
}

// round 11
// speedup vs baseline: 1.0274x; 1.0274x over previous
#include <cuda_runtime.h>
#include <cstdint>

// out[o,m,n] = sum_{kh,j} w0[o,kh,j] * S[m, n+kh, j]       (n >= 1)
// out[o,m,0] = sum_{kh,j} w0[o,kh,j] * S0[m, kh, j]
// Sg (dup-pair u64): row r in [0,63] = S rows, [64,72] = S0 rows.
//   Sg[((m*14 + j)*80) + r] = {S, S} as 2xf32.

__device__ __align__(16) uint64_t Sg[56 * 14 * 80];

__device__ __forceinline__ uint64_t pack2(float s) {
    uint64_t r;
    unsigned u = __float_as_uint(s);
    asm("mov.b64 %0, {%1, %1};" : "=l"(r) : "r"(u));
    return r;
}
__device__ __forceinline__ void ffma2(uint64_t& d, uint64_t a, uint64_t b) {
    asm("fma.rn.f32x2 %0, %1, %2, %0;" : "+l"(d) : "l"(a), "l"(b));
}
__device__ __forceinline__ void addf2(uint64_t& d, uint64_t a) {
    asm("add.rn.f32x2 %0, %0, %1;" : "+l"(d) : "l"(a));
}
__device__ __forceinline__ float2 unpack2(uint64_t v) {
    unsigned lo, hi;
    asm("mov.b64 {%0, %1}, %2;" : "=r"(lo), "=r"(hi) : "l"(v));
    return make_float2(__uint_as_float(lo), __uint_as_float(hi));
}

// ───────────── Kernel 1: build S (dup-pair output) ─────────────
#define XP 68
__global__ __launch_bounds__(160)
void build_S_kernel(const float* __restrict__ x, const float* __restrict__ w1)
{
    __shared__ float xp[24 * XP];   // xp[i][h+5] = x[i,m,h], pads zero
    __shared__ float w1s[24 * 28];
    const int m = blockIdx.x, jg = blockIdx.y, tid = threadIdx.x;

    for (int t = tid; t < 24 * XP; t += 160) xp[t] = 0.0f;
    for (int t = tid; t < 24 * 28; t += 160) w1s[t] = w1[t];
    __syncthreads();
    for (int t = tid; t < 24 * 56; t += 160) {
        const int i = t / 56, h = t % 56;
        xp[i * XP + 5 + h] = x[i * 3136 + m * 56 + h];
    }
    __syncthreads();

    if (tid < 146) {
        const int j = jg * 2 + tid / 73;
        const int r = tid % 73;
        float a0 = 0.f, a1 = 0.f, a2 = 0.f, a3 = 0.f;
        if (r < 64) {
            #pragma unroll
            for (int i = 0; i < 24; i += 2) {
                a0 = fmaf(xp[i * XP + r + 1],     w1s[i * 28 + j],          a0);
                a1 = fmaf(xp[i * XP + r],         w1s[i * 28 + 14 + j],     a1);
                a2 = fmaf(xp[(i+1) * XP + r + 1], w1s[(i+1) * 28 + j],      a2);
                a3 = fmaf(xp[(i+1) * XP + r],     w1s[(i+1) * 28 + 14 + j], a3);
            }
        } else {
            const int kh = r - 64;
            if (kh >= 4) {
                #pragma unroll
                for (int i = 0; i < 24; i += 2) {
                    a0 = fmaf(xp[i * XP + kh + 1],     w1s[i * 28 + j],     a0);
                    a2 = fmaf(xp[(i+1) * XP + kh + 1], w1s[(i+1) * 28 + j], a2);
                }
            }
            if (kh <= 4) {
                #pragma unroll
                for (int i = 0; i < 24; i += 2) {
                    a1 = fmaf(xp[i * XP + kh + 56],     w1s[i * 28 + 14 + j],     a1);
                    a3 = fmaf(xp[(i+1) * XP + kh + 56], w1s[(i+1) * 28 + 14 + j], a3);
                }
            }
        }
        Sg[(m * 14 + j) * 80 + r] = pack2((a0 + a2) + (a1 + a3));
    }
}

// ───────────── Kernel 2: stencil contraction, 16 warps/SM ─────────────
// grid (56 m, 3 og of 32 o, 2 nh of 28 n), block 224 = 16 ow × 7 np × 2 jh.
// Thread: 2 o × 4 n × 7 j × 9 kh. Batched loads per j (30), then 36 FFMA2.
__global__ __launch_bounds__(224, 2)
void contract_kernel(const float* __restrict__ w0, float* __restrict__ out)
{
    __shared__ __align__(16) uint64_t Sd[14 * 80];     // dup-pair S: 8.96 KB
    __shared__ __align__(16) float w0s[126 * 32];      // [k][32 o]: 16.1 KB
    __shared__ __align__(16) uint64_t red[112 * 4];    // jh partials: 3.6 KB

    const int m   = blockIdx.x;
    const int og  = blockIdx.y;          // 0..2
    const int nh  = blockIdx.z;          // 0..1
    const int tid = threadIdx.x;

    // stage Sd: vector copy of dup-pair data (560 ulonglong2)
    {
        const ulonglong2* __restrict__ src =
            reinterpret_cast<const ulonglong2*>(Sg + m * 1120);
        ulonglong2* dst = reinterpret_cast<ulonglong2*>(Sd);
        for (int t = tid; t < 560; t += 224) dst[t] = src[t];
    }
    // stage w0: ol-fast (conflict-free STS, MLP-deep LDG)
    for (int t = tid; t < 126 * 32; t += 224) {
        const int ol = t & 31, k = t >> 5;
        w0s[k * 32 + ol] = w0[(og * 32 + ol) * 126 + k];
    }
    __syncthreads();

    const int ow = tid & 15;             // 0..15 -> o pair
    const int np = (tid >> 4) % 7;       // 0..6  -> n quad
    const int jh = tid / 112;            // 0..1  -> j half
    const int n0 = nh * 28 + 4 * np;
    const int rb  = n0;
    const int rb0 = (n0 == 0) ? 64 : n0; // n==0 -> S0 rows

    uint64_t acc0 = 0, acc1 = 0, acc2 = 0, acc3 = 0;

    #pragma unroll
    for (int j = 0; j < 7; j++) {
        const int jj = jh * 7 + j;
        const uint64_t* __restrict__ sb = Sd + jj * 80;

        uint64_t sw[12];
        #pragma unroll
        for (int d = 0; d < 12; d++) sw[d] = sb[rb + d];
        uint64_t s0w[9];
        #pragma unroll
        for (int d = 0; d < 9; d++) s0w[d] = sb[rb0 + d];
        uint64_t wr[9];
        #pragma unroll
        for (int kh = 0; kh < 9; kh++)
            wr[kh] = *reinterpret_cast<const uint64_t*>(
                w0s + (kh * 14 + jj) * 32 + ow * 2);

        #pragma unroll
        for (int kh = 0; kh < 9; kh++) {
            ffma2(acc0, wr[kh], s0w[kh]);
            ffma2(acc1, wr[kh], sw[1 + kh]);
            ffma2(acc2, wr[kh], sw[2 + kh]);
            ffma2(acc3, wr[kh], sw[3 + kh]);
        }
    }

    const int rr = tid % 112;
    if (jh == 1) {
        ulonglong2* dst = reinterpret_cast<ulonglong2*>(&red[rr * 4]);
        dst[0] = make_ulonglong2(acc0, acc1);
        dst[1] = make_ulonglong2(acc2, acc3);
    }
    __syncthreads();

    if (jh == 0) {
        const ulonglong2* src = reinterpret_cast<const ulonglong2*>(&red[rr * 4]);
        const ulonglong2 p0 = src[0], p1 = src[1];
        addf2(acc0, p0.x);  addf2(acc1, p0.y);
        addf2(acc2, p1.x);  addf2(acc3, p1.y);

        const float2 u0 = unpack2(acc0), u1 = unpack2(acc1);
        const float2 u2 = unpack2(acc2), u3 = unpack2(acc3);
        const int o0 = og * 32 + ow * 2;
        float* op = out + m * 56 + n0;
        *reinterpret_cast<float4*>(op + (o0 + 0) * 3136) =
            make_float4(u0.x, u1.x, u2.x, u3.x);
        *reinterpret_cast<float4*>(op + (o0 + 1) * 3136) =
            make_float4(u0.y, u1.y, u2.y, u3.y);
    }
}

extern "C" void kernel_launch(void* const* d_in, const int* in_sizes, int n_in,
                              void* d_out, int out_size)
{
    const float* x = (const float*)d_in[0];
    const float* w0;
    const float* w1;
    if (in_sizes[1] == 12096) { w0 = (const float*)d_in[1]; w1 = (const float*)d_in[2]; }
    else                      { w0 = (const float*)d_in[2]; w1 = (const float*)d_in[1]; }
    float* out = (float*)d_out;

    build_S_kernel<<<dim3(56, 7), 160>>>(x, w1);
    contract_kernel<<<dim3(56, 3, 2), 224>>>(w0, out);
}